// round 2
// baseline (speedup 1.0000x reference)
#include <cuda_runtime.h>
#include <math.h>

// Problem constants
#define BB 2
#define LL 2048
#define DD 4096
#define HH 32
#define HDIM 128
#define MM (BB*LL)          // 4096 rows
#define ATT_SCALE 0.08838834764831845f

// Scratch (allocation-free rule: __device__ globals)
__device__ float g_q[(size_t)BB*HH*LL*HDIM];     // 64 MB
__device__ float g_ctx[(size_t)BB*LL*DD];        // 64 MB

// ---------------------------------------------------------------------------
// GEMM: out = A[M,K] @ W[K,N] + bias[N],  M=N=K=4096
// out_mode 0: row-major [M,N]
// out_mode 1: head-split [B,H,L,d] (n0 tile aligns with one head since BN=128)
// ---------------------------------------------------------------------------
__global__ __launch_bounds__(256) void gemm_bias_kernel(
    const float* __restrict__ A, const float* __restrict__ W,
    const float* __restrict__ bias, float* __restrict__ out, int out_mode)
{
    const int K = 4096, N = 4096;
    __shared__ __align__(16) float As[16][128];
    __shared__ __align__(16) float Bs[16][128];

    const int tid = threadIdx.x;
    const int tx = tid & 15;
    const int ty = tid >> 4;
    const int m0 = blockIdx.y * 128;
    const int n0 = blockIdx.x * 128;

    float c[8][8];
#pragma unroll
    for (int i = 0; i < 8; i++)
#pragma unroll
        for (int j = 0; j < 8; j++) c[i][j] = 0.f;

    for (int k0 = 0; k0 < K; k0 += 16) {
        // Load A tile (128 rows x 16 cols), transpose into As[k][m]
#pragma unroll
        for (int i = 0; i < 2; i++) {
            int f = tid + i * 256;            // 0..511 float4 ids
            int row = f >> 2;
            int kc = (f & 3) << 2;
            float4 v = *(const float4*)&A[(size_t)(m0 + row) * K + k0 + kc];
            As[kc + 0][row] = v.x;
            As[kc + 1][row] = v.y;
            As[kc + 2][row] = v.z;
            As[kc + 3][row] = v.w;
        }
        // Load B tile (16 rows x 128 cols)
#pragma unroll
        for (int i = 0; i < 2; i++) {
            int f = tid + i * 256;
            int krow = f >> 5;
            int nc = (f & 31) << 2;
            *(float4*)&Bs[krow][nc] = *(const float4*)&W[(size_t)(k0 + krow) * N + n0 + nc];
        }
        __syncthreads();

#pragma unroll
        for (int kk = 0; kk < 16; kk++) {
            float a[8], b[8];
            *(float4*)&a[0] = *(const float4*)&As[kk][ty * 4];
            *(float4*)&a[4] = *(const float4*)&As[kk][64 + ty * 4];
            *(float4*)&b[0] = *(const float4*)&Bs[kk][tx * 4];
            *(float4*)&b[4] = *(const float4*)&Bs[kk][64 + tx * 4];
#pragma unroll
            for (int i = 0; i < 8; i++)
#pragma unroll
                for (int j = 0; j < 8; j++)
                    c[i][j] += a[i] * b[j];
        }
        __syncthreads();
    }

    // Epilogue: bias + store
#pragma unroll
    for (int i = 0; i < 8; i++) {
        int rloc = (i < 4) ? (ty * 4 + i) : (64 + ty * 4 + (i - 4));
        int row = m0 + rloc;
#pragma unroll
        for (int jg = 0; jg < 2; jg++) {
            int col = (jg == 0) ? (tx * 4) : (64 + tx * 4);
            float4 v;
            v.x = c[i][jg * 4 + 0] + bias[n0 + col + 0];
            v.y = c[i][jg * 4 + 1] + bias[n0 + col + 1];
            v.z = c[i][jg * 4 + 2] + bias[n0 + col + 2];
            v.w = c[i][jg * 4 + 3] + bias[n0 + col + 3];
            if (out_mode == 0) {
                *(float4*)&out[(size_t)row * N + n0 + col] = v;
            } else {
                int b_  = row >> 11;          // row / 2048
                int l_  = row & 2047;
                int h_  = n0 >> 7;            // head index; col in [0,128) is dd
                size_t idx = ((((size_t)b_ * HH + h_) * LL + l_) * HDIM) + col;
                *(float4*)&out[idx] = v;
            }
        }
    }
}

// ---------------------------------------------------------------------------
// Flash attention (causal), fp32.
// Grid: (L/64, H, B). Block: 256 threads.
// Thread (tr=tid/16, tc=tid%16):
//   score tile rows R_i = tr+16i (i<4), cols C_j = tc+16j (j<4)
//   O tile  rows R_i,  cols g*64 + tc*4 + e (g<2, e<4)
// Smem rows padded to 132 floats so 16-strided indices hit distinct banks.
// ---------------------------------------------------------------------------
#define QROWSTR 132
#define SROWSTR 65
#define ATT_SMEM_FLOATS (3 * 64 * QROWSTR + 64 * SROWSTR)

__global__ __launch_bounds__(256) void attn_kernel(
    const float* __restrict__ qg, const float* __restrict__ kg,
    const float* __restrict__ vg, float* __restrict__ ctx)
{
    extern __shared__ __align__(16) float sm[];
    float* Qs = sm;                       // 64 x 132
    float* Ks = Qs + 64 * QROWSTR;        // 64 x 132
    float* Vs = Ks + 64 * QROWSTR;        // 64 x 132
    float* Ss = Vs + 64 * QROWSTR;        // 64 x 65

    const int tid = threadIdx.x;
    const int tc = tid & 15;
    const int tr = tid >> 4;

    const int qt = blockIdx.x;
    const int h  = blockIdx.y;
    const int b  = blockIdx.z;
    const int q0 = qt * 64;

    const float* qb = qg + ((size_t)b * HH + h) * LL * HDIM;
    const float* kb = kg + ((size_t)b * HH + h) * LL * HDIM;
    const float* vb = vg + ((size_t)b * HH + h) * LL * HDIM;

    // Load Q tile
#pragma unroll
    for (int i = 0; i < 8; i++) {
        int f = tid + i * 256;            // 2048 float4s
        int row = f >> 5;
        int c4 = (f & 31) << 2;
        *(float4*)&Qs[row * QROWSTR + c4] =
            *(const float4*)&qb[(size_t)(q0 + row) * HDIM + c4];
    }

    float m_i[4], l_i[4], o[4][8];
#pragma unroll
    for (int i = 0; i < 4; i++) {
        m_i[i] = -1e30f;
        l_i[i] = 0.f;
#pragma unroll
        for (int j = 0; j < 8; j++) o[i][j] = 0.f;
    }

    for (int kt = 0; kt <= qt; kt++) {
        const int k0 = kt * 64;
        __syncthreads();   // previous PV done with Vs; also publishes Qs on iter 0
#pragma unroll
        for (int i = 0; i < 8; i++) {
            int f = tid + i * 256;
            int row = f >> 5;
            int c4 = (f & 31) << 2;
            *(float4*)&Ks[row * QROWSTR + c4] =
                *(const float4*)&kb[(size_t)(k0 + row) * HDIM + c4];
            *(float4*)&Vs[row * QROWSTR + c4] =
                *(const float4*)&vb[(size_t)(k0 + row) * HDIM + c4];
        }
        __syncthreads();

        // ---- scores ----
        float s[4][4];
#pragma unroll
        for (int i = 0; i < 4; i++)
#pragma unroll
            for (int j = 0; j < 4; j++) s[i][j] = 0.f;

#pragma unroll 4
        for (int k4 = 0; k4 < 32; k4++) {
            float4 a[4], bf[4];
#pragma unroll
            for (int i = 0; i < 4; i++)
                a[i] = *(const float4*)&Qs[(tr + 16 * i) * QROWSTR + k4 * 4];
#pragma unroll
            for (int j = 0; j < 4; j++)
                bf[j] = *(const float4*)&Ks[(tc + 16 * j) * QROWSTR + k4 * 4];
#pragma unroll
            for (int i = 0; i < 4; i++)
#pragma unroll
                for (int j = 0; j < 4; j++)
                    s[i][j] += a[i].x * bf[j].x + a[i].y * bf[j].y +
                               a[i].z * bf[j].z + a[i].w * bf[j].w;
        }

        const bool diag = (kt == qt);
#pragma unroll
        for (int i = 0; i < 4; i++) {
            int R = tr + 16 * i;
#pragma unroll
            for (int j = 0; j < 4; j++) {
                int C = tc + 16 * j;
                float val = s[i][j] * ATT_SCALE;
                if (diag && (k0 + C) > (q0 + R)) val = -1e30f;
                s[i][j] = val;
            }
        }

        // ---- online softmax (per row; 16 tc lanes of same tr cooperate) ----
#pragma unroll
        for (int i = 0; i < 4; i++) {
            float mx = fmaxf(fmaxf(s[i][0], s[i][1]), fmaxf(s[i][2], s[i][3]));
#pragma unroll
            for (int off = 1; off < 16; off <<= 1)
                mx = fmaxf(mx, __shfl_xor_sync(0xffffffffu, mx, off));
            float m_new = fmaxf(m_i[i], mx);
            float scl = __expf(m_i[i] - m_new);
            float rs = 0.f;
#pragma unroll
            for (int j = 0; j < 4; j++) {
                float p = __expf(s[i][j] - m_new);
                Ss[(tr + 16 * i) * SROWSTR + (tc + 16 * j)] = p;
                rs += p;
            }
#pragma unroll
            for (int off = 1; off < 16; off <<= 1)
                rs += __shfl_xor_sync(0xffffffffu, rs, off);
            l_i[i] = l_i[i] * scl + rs;
            m_i[i] = m_new;
#pragma unroll
            for (int j = 0; j < 8; j++) o[i][j] *= scl;
        }
        __syncwarp();   // Ss rows are produced & consumed within the same warp

        // ---- PV: o[R_i][g*64 + tc*4 + e] += P[R_i][c] * V[c][col] ----
#pragma unroll 4
        for (int c = 0; c < 64; c++) {
            float p0 = Ss[(tr +  0) * SROWSTR + c];
            float p1 = Ss[(tr + 16) * SROWSTR + c];
            float p2 = Ss[(tr + 32) * SROWSTR + c];
            float p3 = Ss[(tr + 48) * SROWSTR + c];
            float4 v0 = *(const float4*)&Vs[c * QROWSTR + tc * 4];
            float4 v1 = *(const float4*)&Vs[c * QROWSTR + 64 + tc * 4];
            o[0][0] += p0 * v0.x; o[0][1] += p0 * v0.y; o[0][2] += p0 * v0.z; o[0][3] += p0 * v0.w;
            o[0][4] += p0 * v1.x; o[0][5] += p0 * v1.y; o[0][6] += p0 * v1.z; o[0][7] += p0 * v1.w;
            o[1][0] += p1 * v0.x; o[1][1] += p1 * v0.y; o[1][2] += p1 * v0.z; o[1][3] += p1 * v0.w;
            o[1][4] += p1 * v1.x; o[1][5] += p1 * v1.y; o[1][6] += p1 * v1.z; o[1][7] += p1 * v1.w;
            o[2][0] += p2 * v0.x; o[2][1] += p2 * v0.y; o[2][2] += p2 * v0.z; o[2][3] += p2 * v0.w;
            o[2][4] += p2 * v1.x; o[2][5] += p2 * v1.y; o[2][6] += p2 * v1.z; o[2][7] += p2 * v1.w;
            o[3][0] += p3 * v0.x; o[3][1] += p3 * v0.y; o[3][2] += p3 * v0.z; o[3][3] += p3 * v0.w;
            o[3][4] += p3 * v1.x; o[3][5] += p3 * v1.y; o[3][6] += p3 * v1.z; o[3][7] += p3 * v1.w;
        }
    }

    // ---- write context in [B, L, H*d] layout ----
#pragma unroll
    for (int i = 0; i < 4; i++) {
        int row = q0 + tr + 16 * i;
        float inv = 1.0f / l_i[i];
        size_t base = ((size_t)b * LL + row) * DD + h * HDIM;
        float4 v;
        v.x = o[i][0] * inv; v.y = o[i][1] * inv; v.z = o[i][2] * inv; v.w = o[i][3] * inv;
        *(float4*)&ctx[base + tc * 4] = v;
        v.x = o[i][4] * inv; v.y = o[i][5] * inv; v.z = o[i][6] * inv; v.w = o[i][7] * inv;
        *(float4*)&ctx[base + 64 + tc * 4] = v;
    }
}

// ---------------------------------------------------------------------------
// Launch: q/k/v projections -> attention -> output projection.
// d_out layout: [ out (B*L*D) | k (B*H*L*d) | v (B*H*L*d) ]
// ---------------------------------------------------------------------------
extern "C" void kernel_launch(void* const* d_in, const int* in_sizes, int n_in,
                              void* d_out, int out_size)
{
    const float* x  = (const float*)d_in[0];
    // d_in[1] = mask (int32) — causal structure is known, unused
    const float* Wq = (const float*)d_in[2];
    const float* bq = (const float*)d_in[3];
    const float* Wk = (const float*)d_in[4];
    const float* bk = (const float*)d_in[5];
    const float* Wv = (const float*)d_in[6];
    const float* bv = (const float*)d_in[7];
    const float* Wo = (const float*)d_in[8];
    const float* bo = (const float*)d_in[9];

    float* out_p = (float*)d_out;
    float* k_out = out_p + (size_t)BB * LL * DD;
    float* v_out = k_out + (size_t)BB * HH * LL * HDIM;

    float* qbuf   = nullptr;
    float* ctxbuf = nullptr;
    cudaGetSymbolAddress((void**)&qbuf, g_q);
    cudaGetSymbolAddress((void**)&ctxbuf, g_ctx);

    dim3 gg(DD / 128, MM / 128);

    gemm_bias_kernel<<<gg, 256>>>(x, Wq, bq, qbuf, 1);
    gemm_bias_kernel<<<gg, 256>>>(x, Wk, bk, k_out, 1);
    gemm_bias_kernel<<<gg, 256>>>(x, Wv, bv, v_out, 1);

    size_t smem = (size_t)ATT_SMEM_FLOATS * sizeof(float);   // ~115 KB
    cudaFuncSetAttribute(attn_kernel, cudaFuncAttributeMaxDynamicSharedMemorySize, (int)smem);
    dim3 ag(LL / 64, HH, BB);
    attn_kernel<<<ag, 256, smem>>>(qbuf, k_out, v_out, ctxbuf);

    gemm_bias_kernel<<<gg, 256>>>(ctxbuf, Wo, bo, out_p, 0);
}

// round 4
// speedup vs baseline: 1.9866x; 1.9866x over previous
#include <cuda_runtime.h>
#include <cuda_bf16.h>
#include <math.h>
#include <stdint.h>

// Problem constants
#define BB 2
#define LL 2048
#define DD 4096
#define HH 32
#define HDIM 128
#define MM (BB*LL)          // 4096 rows
#define ATT_SCALE 0.08838834764831845f

// ---------------------------------------------------------------------------
// Scratch (allocation-free rule: __device__ globals)
// ---------------------------------------------------------------------------
__device__ float g_q[(size_t)BB*HH*LL*HDIM];                 // 64 MB
__device__ float g_ctx[(size_t)BB*LL*DD];                    // 64 MB
__device__ __nv_bfloat16 g_ah[(size_t)MM*DD];                // A hi (x or ctx)
__device__ __nv_bfloat16 g_al[(size_t)MM*DD];                // A lo
__device__ __nv_bfloat16 g_bh[(size_t)DD*DD];                // W^T hi  [N,K]
__device__ __nv_bfloat16 g_bl[(size_t)DD*DD];                // W^T lo  [N,K]

__device__ __forceinline__ uint32_t smem_u32(const void* p) {
    uint32_t a;
    asm("{ .reg .u64 t; cvta.to.shared.u64 t, %1; cvt.u32.u64 %0, t; }"
        : "=r"(a) : "l"(p));
    return a;
}

#define LDSM4(r, addr) \
    asm volatile("ldmatrix.sync.aligned.m8n8.x4.shared.b16 {%0,%1,%2,%3}, [%4];" \
        : "=r"((r)[0]), "=r"((r)[1]), "=r"((r)[2]), "=r"((r)[3]) : "r"(addr))

#define MMA_BF16(d, a, b0, b1) \
    asm volatile("mma.sync.aligned.m16n8k16.row.col.f32.bf16.bf16.f32 " \
        "{%0,%1,%2,%3}, {%4,%5,%6,%7}, {%8,%9}, {%0,%1,%2,%3};" \
        : "+f"((d)[0]), "+f"((d)[1]), "+f"((d)[2]), "+f"((d)[3]) \
        : "r"((a)[0]), "r"((a)[1]), "r"((a)[2]), "r"((a)[3]), "r"(b0), "r"(b1))

#define CP_ASYNC16(dst, src) \
    asm volatile("cp.async.cg.shared.global [%0], [%1], 16;" \
        :: "r"(dst), "l"(src) : "memory")
#define CP_COMMIT() asm volatile("cp.async.commit_group;" ::: "memory")
#define CP_WAIT1() asm volatile("cp.async.wait_group 1;" ::: "memory")
#define CP_WAIT0() asm volatile("cp.async.wait_group 0;" ::: "memory")

// ---------------------------------------------------------------------------
// Conversion kernels (fp32 -> bf16 hi/lo split)
// ---------------------------------------------------------------------------
struct __align__(8) bf16x4 { __nv_bfloat16 v[4]; };

__global__ __launch_bounds__(256) void conv_split_kernel(
    const float4* __restrict__ in, bf16x4* __restrict__ oh, bf16x4* __restrict__ ol, int n4)
{
    int i = blockIdx.x * 256 + threadIdx.x;
    if (i >= n4) return;
    float4 x = in[i];
    bf16x4 h, l;
    h.v[0] = __float2bfloat16_rn(x.x); l.v[0] = __float2bfloat16_rn(x.x - __bfloat162float(h.v[0]));
    h.v[1] = __float2bfloat16_rn(x.y); l.v[1] = __float2bfloat16_rn(x.y - __bfloat162float(h.v[1]));
    h.v[2] = __float2bfloat16_rn(x.z); l.v[2] = __float2bfloat16_rn(x.z - __bfloat162float(h.v[2]));
    h.v[3] = __float2bfloat16_rn(x.w); l.v[3] = __float2bfloat16_rn(x.w - __bfloat162float(h.v[3]));
    oh[i] = h;
    ol[i] = l;
}

// W [K,N] f32 row-major -> Wt hi/lo [N,K] bf16
__global__ __launch_bounds__(256) void conv_tr_kernel(
    const float* __restrict__ W, __nv_bfloat16* __restrict__ Th, __nv_bfloat16* __restrict__ Tl)
{
    __shared__ float sm[32][33];
    const int k0 = blockIdx.x * 32, n0 = blockIdx.y * 32;
    const int tx = threadIdx.x, ty = threadIdx.y;     // (32, 8)
#pragma unroll
    for (int i = 0; i < 4; i++)
        sm[ty + 8 * i][tx] = W[(size_t)(k0 + ty + 8 * i) * DD + n0 + tx];
    __syncthreads();
#pragma unroll
    for (int i = 0; i < 4; i++) {
        float v = sm[tx][ty + 8 * i];
        __nv_bfloat16 h = __float2bfloat16_rn(v);
        __nv_bfloat16 l = __float2bfloat16_rn(v - __bfloat162float(h));
        size_t idx = (size_t)(n0 + ty + 8 * i) * DD + k0 + tx;
        Th[idx] = h;
        Tl[idx] = l;
    }
}

// ---------------------------------------------------------------------------
// HMMA GEMM: out[M,N] = A[M,K] @ W[K,N] + bias, via hi/lo bf16 3-term split.
// A as (Ah, Al) row-major [M,K]; W as (Bh, Bl) transposed [N,K].
// CTA 128x128, 8 warps (2x4), warp tile 64x32, K-chunk 64, cp.async 2-stage.
// SMEM tile rows padded: 64 bf16 data + 8 pad = 144 B row stride.
// out_mode 0: row-major [M,N]; 1: head-split [B,H,L,d].
// ---------------------------------------------------------------------------
#define KCH 64
#define ROWSTR_B 144
#define TILE_BYTES (128 * ROWSTR_B)       // 18432
#define STAGE_BYTES (4 * TILE_BYTES)      // 73728  (Ah, Al, Bh, Bl)
#define GEMM_SMEM (2 * STAGE_BYTES)       // 147456
#define NCHUNK (DD / KCH)                 // 64

__global__ __launch_bounds__(256, 1) void gemm_mma_kernel(
    const __nv_bfloat16* __restrict__ Ah, const __nv_bfloat16* __restrict__ Al,
    const __nv_bfloat16* __restrict__ Bh, const __nv_bfloat16* __restrict__ Bl,
    const float* __restrict__ bias, float* __restrict__ out, int out_mode)
{
    extern __shared__ __align__(16) char smem[];
    const uint32_t sb = smem_u32(smem);
    const int tid = threadIdx.x, lane = tid & 31, wid = tid >> 5;
    const int wm = wid >> 2;              // 0..1
    const int wn = wid & 3;               // 0..3
    const int m0 = blockIdx.y * 128;
    const int n0 = blockIdx.x * 128;

    const __nv_bfloat16* gsrc[4];
    gsrc[0] = Ah + (size_t)m0 * DD;
    gsrc[1] = Al + (size_t)m0 * DD;
    gsrc[2] = Bh + (size_t)n0 * DD;
    gsrc[3] = Bl + (size_t)n0 * DD;

    float acc[4][4][4];
#pragma unroll
    for (int i = 0; i < 4; i++)
#pragma unroll
        for (int j = 0; j < 4; j++)
#pragma unroll
            for (int e = 0; e < 4; e++) acc[i][j][e] = 0.f;

    // per-thread ldmatrix base offsets (within a stage)
    // A: lanes 0-15 -> rows 0-15 (k lo), lanes 16-31 -> rows 0-15 (k hi)
    const uint32_t a_off = (uint32_t)(wm * 64 + (lane & 15)) * ROWSTR_B + ((lane >> 4) << 4);
    // B: row = wn*32 + ((lane>>4)<<3) + (lane&7); col-half = (lane>>3)&1
    const uint32_t b_off = (uint32_t)(wn * 32 + ((lane >> 4) << 3) + (lane & 7)) * ROWSTR_B
                           + (((lane >> 3) & 1) << 4);

#define LOAD_CHUNK(cc, buf) do {                                               \
    const uint32_t stage_ = sb + (uint32_t)(buf) * STAGE_BYTES;                \
    _Pragma("unroll")                                                          \
    for (int t_ = 0; t_ < 4; ++t_) {                                           \
        const __nv_bfloat16* gp_ = gsrc[t_] + (size_t)(cc) * KCH;              \
        _Pragma("unroll")                                                      \
        for (int i_ = 0; i_ < 4; ++i_) {                                       \
            int f_ = tid + i_ * 256;                                           \
            int r_ = f_ >> 3, s_ = f_ & 7;                                     \
            const void* src_ = gp_ + (size_t)r_ * DD + s_ * 8;                 \
            uint32_t dst_ = stage_ + t_ * TILE_BYTES + r_ * ROWSTR_B + s_ * 16;\
            CP_ASYNC16(dst_, src_);                                            \
        }                                                                      \
    }                                                                          \
    CP_COMMIT();                                                               \
} while (0)

    LOAD_CHUNK(0, 0);

#pragma unroll 1
    for (int c = 0; c < NCHUNK; ++c) {
        if (c + 1 < NCHUNK) {
            LOAD_CHUNK(c + 1, (c + 1) & 1);
            CP_WAIT1();
        } else {
            CP_WAIT0();
        }
        __syncthreads();

        const uint32_t stage = sb + (uint32_t)(c & 1) * STAGE_BYTES;
        const uint32_t a_h = stage + a_off;
        const uint32_t a_l = stage + TILE_BYTES + a_off;
        const uint32_t b_h = stage + 2 * TILE_BYTES + b_off;
        const uint32_t b_l = stage + 3 * TILE_BYTES + b_off;

#pragma unroll
        for (int kk = 0; kk < 4; ++kk) {
            uint32_t ah_[4][4], al_[4][4], bh_[2][4], bl_[2][4];
#pragma unroll
            for (int i = 0; i < 4; ++i) {
                LDSM4(ah_[i], a_h + i * 16 * ROWSTR_B + kk * 32);
                LDSM4(al_[i], a_l + i * 16 * ROWSTR_B + kk * 32);
            }
#pragma unroll
            for (int j = 0; j < 2; ++j) {
                LDSM4(bh_[j], b_h + j * 16 * ROWSTR_B + kk * 32);
                LDSM4(bl_[j], b_l + j * 16 * ROWSTR_B + kk * 32);
            }
            // product-major order: same-acc MMAs are 16 issues apart
#pragma unroll
            for (int i = 0; i < 4; ++i)
#pragma unroll
                for (int jn = 0; jn < 4; ++jn)
                    MMA_BF16(acc[i][jn], ah_[i], bh_[jn >> 1][(jn & 1) * 2],
                             bh_[jn >> 1][(jn & 1) * 2 + 1]);
#pragma unroll
            for (int i = 0; i < 4; ++i)
#pragma unroll
                for (int jn = 0; jn < 4; ++jn)
                    MMA_BF16(acc[i][jn], ah_[i], bl_[jn >> 1][(jn & 1) * 2],
                             bl_[jn >> 1][(jn & 1) * 2 + 1]);
#pragma unroll
            for (int i = 0; i < 4; ++i)
#pragma unroll
                for (int jn = 0; jn < 4; ++jn)
                    MMA_BF16(acc[i][jn], al_[i], bh_[jn >> 1][(jn & 1) * 2],
                             bh_[jn >> 1][(jn & 1) * 2 + 1]);
        }
        __syncthreads();
    }
#undef LOAD_CHUNK

    // epilogue
#pragma unroll
    for (int i = 0; i < 4; ++i) {
        const int r_lo = m0 + wm * 64 + i * 16 + (lane >> 2);
#pragma unroll
        for (int jn = 0; jn < 4; ++jn) {
            const int colg = n0 + wn * 32 + jn * 8 + (lane & 3) * 2;
            const float bv0 = bias[colg], bv1 = bias[colg + 1];
#pragma unroll
            for (int half = 0; half < 2; ++half) {
                const int row = r_lo + half * 8;
                float2 v;
                v.x = acc[i][jn][half * 2 + 0] + bv0;
                v.y = acc[i][jn][half * 2 + 1] + bv1;
                float* dst;
                if (out_mode == 0) {
                    dst = out + (size_t)row * DD + colg;
                } else {
                    int b_ = row >> 11, l_ = row & 2047, h_ = colg >> 7, dd = colg & 127;
                    dst = out + ((((size_t)b_ * HH + h_) * LL + l_) * HDIM) + dd;
                }
                *(float2*)dst = v;
            }
        }
    }
}

// ---------------------------------------------------------------------------
// Flash attention (causal), fp32 — unchanged (known good).
// ---------------------------------------------------------------------------
#define QROWSTR 132
#define SROWSTR 65
#define ATT_SMEM_FLOATS (3 * 64 * QROWSTR + 64 * SROWSTR)

__global__ __launch_bounds__(256) void attn_kernel(
    const float* __restrict__ qg, const float* __restrict__ kg,
    const float* __restrict__ vg, float* __restrict__ ctx)
{
    extern __shared__ __align__(16) float sm[];
    float* Qs = sm;
    float* Ks = Qs + 64 * QROWSTR;
    float* Vs = Ks + 64 * QROWSTR;
    float* Ss = Vs + 64 * QROWSTR;

    const int tid = threadIdx.x;
    const int tc = tid & 15;
    const int tr = tid >> 4;

    const int qt = blockIdx.x;
    const int h  = blockIdx.y;
    const int b  = blockIdx.z;
    const int q0 = qt * 64;

    const float* qb = qg + ((size_t)b * HH + h) * LL * HDIM;
    const float* kb = kg + ((size_t)b * HH + h) * LL * HDIM;
    const float* vb = vg + ((size_t)b * HH + h) * LL * HDIM;

#pragma unroll
    for (int i = 0; i < 8; i++) {
        int f = tid + i * 256;
        int row = f >> 5;
        int c4 = (f & 31) << 2;
        *(float4*)&Qs[row * QROWSTR + c4] =
            *(const float4*)&qb[(size_t)(q0 + row) * HDIM + c4];
    }

    float m_i[4], l_i[4], o[4][8];
#pragma unroll
    for (int i = 0; i < 4; i++) {
        m_i[i] = -1e30f;
        l_i[i] = 0.f;
#pragma unroll
        for (int j = 0; j < 8; j++) o[i][j] = 0.f;
    }

    for (int kt = 0; kt <= qt; kt++) {
        const int k0 = kt * 64;
        __syncthreads();
#pragma unroll
        for (int i = 0; i < 8; i++) {
            int f = tid + i * 256;
            int row = f >> 5;
            int c4 = (f & 31) << 2;
            *(float4*)&Ks[row * QROWSTR + c4] =
                *(const float4*)&kb[(size_t)(k0 + row) * HDIM + c4];
            *(float4*)&Vs[row * QROWSTR + c4] =
                *(const float4*)&vb[(size_t)(k0 + row) * HDIM + c4];
        }
        __syncthreads();

        float s[4][4];
#pragma unroll
        for (int i = 0; i < 4; i++)
#pragma unroll
            for (int j = 0; j < 4; j++) s[i][j] = 0.f;

#pragma unroll 4
        for (int k4 = 0; k4 < 32; k4++) {
            float4 a[4], bf[4];
#pragma unroll
            for (int i = 0; i < 4; i++)
                a[i] = *(const float4*)&Qs[(tr + 16 * i) * QROWSTR + k4 * 4];
#pragma unroll
            for (int j = 0; j < 4; j++)
                bf[j] = *(const float4*)&Ks[(tc + 16 * j) * QROWSTR + k4 * 4];
#pragma unroll
            for (int i = 0; i < 4; i++)
#pragma unroll
                for (int j = 0; j < 4; j++)
                    s[i][j] += a[i].x * bf[j].x + a[i].y * bf[j].y +
                               a[i].z * bf[j].z + a[i].w * bf[j].w;
        }

        const bool diag = (kt == qt);
#pragma unroll
        for (int i = 0; i < 4; i++) {
            int R = tr + 16 * i;
#pragma unroll
            for (int j = 0; j < 4; j++) {
                int C = tc + 16 * j;
                float val = s[i][j] * ATT_SCALE;
                if (diag && (k0 + C) > (q0 + R)) val = -1e30f;
                s[i][j] = val;
            }
        }

#pragma unroll
        for (int i = 0; i < 4; i++) {
            float mx = fmaxf(fmaxf(s[i][0], s[i][1]), fmaxf(s[i][2], s[i][3]));
#pragma unroll
            for (int off = 1; off < 16; off <<= 1)
                mx = fmaxf(mx, __shfl_xor_sync(0xffffffffu, mx, off));
            float m_new = fmaxf(m_i[i], mx);
            float scl = __expf(m_i[i] - m_new);
            float rs = 0.f;
#pragma unroll
            for (int j = 0; j < 4; j++) {
                float p = __expf(s[i][j] - m_new);
                Ss[(tr + 16 * i) * SROWSTR + (tc + 16 * j)] = p;
                rs += p;
            }
#pragma unroll
            for (int off = 1; off < 16; off <<= 1)
                rs += __shfl_xor_sync(0xffffffffu, rs, off);
            l_i[i] = l_i[i] * scl + rs;
            m_i[i] = m_new;
#pragma unroll
            for (int j = 0; j < 8; j++) o[i][j] *= scl;
        }
        __syncwarp();

#pragma unroll 4
        for (int c = 0; c < 64; c++) {
            float p0 = Ss[(tr +  0) * SROWSTR + c];
            float p1 = Ss[(tr + 16) * SROWSTR + c];
            float p2 = Ss[(tr + 32) * SROWSTR + c];
            float p3 = Ss[(tr + 48) * SROWSTR + c];
            float4 v0 = *(const float4*)&Vs[c * QROWSTR + tc * 4];
            float4 v1 = *(const float4*)&Vs[c * QROWSTR + 64 + tc * 4];
            o[0][0] += p0 * v0.x; o[0][1] += p0 * v0.y; o[0][2] += p0 * v0.z; o[0][3] += p0 * v0.w;
            o[0][4] += p0 * v1.x; o[0][5] += p0 * v1.y; o[0][6] += p0 * v1.z; o[0][7] += p0 * v1.w;
            o[1][0] += p1 * v0.x; o[1][1] += p1 * v0.y; o[1][2] += p1 * v0.z; o[1][3] += p1 * v0.w;
            o[1][4] += p1 * v1.x; o[1][5] += p1 * v1.y; o[1][6] += p1 * v1.z; o[1][7] += p1 * v1.w;
            o[2][0] += p2 * v0.x; o[2][1] += p2 * v0.y; o[2][2] += p2 * v0.z; o[2][3] += p2 * v0.w;
            o[2][4] += p2 * v1.x; o[2][5] += p2 * v1.y; o[2][6] += p2 * v1.z; o[2][7] += p2 * v1.w;
            o[3][0] += p3 * v0.x; o[3][1] += p3 * v0.y; o[3][2] += p3 * v0.z; o[3][3] += p3 * v0.w;
            o[3][4] += p3 * v1.x; o[3][5] += p3 * v1.y; o[3][6] += p3 * v1.z; o[3][7] += p3 * v1.w;
        }
    }

#pragma unroll
    for (int i = 0; i < 4; i++) {
        int row = q0 + tr + 16 * i;
        float inv = 1.0f / l_i[i];
        size_t base = ((size_t)b * LL + row) * DD + h * HDIM;
        float4 v;
        v.x = o[i][0] * inv; v.y = o[i][1] * inv; v.z = o[i][2] * inv; v.w = o[i][3] * inv;
        *(float4*)&ctx[base + tc * 4] = v;
        v.x = o[i][4] * inv; v.y = o[i][5] * inv; v.z = o[i][6] * inv; v.w = o[i][7] * inv;
        *(float4*)&ctx[base + 64 + tc * 4] = v;
    }
}

// ---------------------------------------------------------------------------
// Launch
// d_out layout: [ out (B*L*D) | k (B*H*L*d) | v (B*H*L*d) ]
// ---------------------------------------------------------------------------
extern "C" void kernel_launch(void* const* d_in, const int* in_sizes, int n_in,
                              void* d_out, int out_size)
{
    const float* x  = (const float*)d_in[0];
    const float* Wq = (const float*)d_in[2];
    const float* bq = (const float*)d_in[3];
    const float* Wk = (const float*)d_in[4];
    const float* bk = (const float*)d_in[5];
    const float* Wv = (const float*)d_in[6];
    const float* bv = (const float*)d_in[7];
    const float* Wo = (const float*)d_in[8];
    const float* bo = (const float*)d_in[9];

    float* out_p = (float*)d_out;
    float* k_out = out_p + (size_t)BB * LL * DD;
    float* v_out = k_out + (size_t)BB * HH * LL * HDIM;

    float *qbuf, *ctxbuf;
    __nv_bfloat16 *ah, *al, *bh, *bl;
    cudaGetSymbolAddress((void**)&qbuf, g_q);
    cudaGetSymbolAddress((void**)&ctxbuf, g_ctx);
    cudaGetSymbolAddress((void**)&ah, g_ah);
    cudaGetSymbolAddress((void**)&al, g_al);
    cudaGetSymbolAddress((void**)&bh, g_bh);
    cudaGetSymbolAddress((void**)&bl, g_bl);

    cudaFuncSetAttribute(gemm_mma_kernel, cudaFuncAttributeMaxDynamicSharedMemorySize, GEMM_SMEM);
    size_t att_smem = (size_t)ATT_SMEM_FLOATS * sizeof(float);
    cudaFuncSetAttribute(attn_kernel, cudaFuncAttributeMaxDynamicSharedMemorySize, (int)att_smem);

    const int n4 = MM * DD / 4;
    const int cs_blocks = n4 / 256;
    dim3 tr_grid(DD / 32, DD / 32);
    dim3 tr_block(32, 8);
    dim3 gg(DD / 128, MM / 128);

    // split A = x
    conv_split_kernel<<<cs_blocks, 256>>>((const float4*)x, (bf16x4*)ah, (bf16x4*)al, n4);

    // Q projection -> g_q (head-split)
    conv_tr_kernel<<<tr_grid, tr_block>>>(Wq, bh, bl);
    gemm_mma_kernel<<<gg, 256, GEMM_SMEM>>>(ah, al, bh, bl, bq, qbuf, 1);

    // K projection -> k_out (head-split)
    conv_tr_kernel<<<tr_grid, tr_block>>>(Wk, bh, bl);
    gemm_mma_kernel<<<gg, 256, GEMM_SMEM>>>(ah, al, bh, bl, bk, k_out, 1);

    // V projection -> v_out (head-split)
    conv_tr_kernel<<<tr_grid, tr_block>>>(Wv, bh, bl);
    gemm_mma_kernel<<<gg, 256, GEMM_SMEM>>>(ah, al, bh, bl, bv, v_out, 1);

    // attention (fp32)
    dim3 ag(LL / 64, HH, BB);
    attn_kernel<<<ag, 256, att_smem>>>(qbuf, k_out, v_out, ctxbuf);

    // split A = ctx, output projection -> out
    conv_split_kernel<<<cs_blocks, 256>>>((const float4*)ctxbuf, (bf16x4*)ah, (bf16x4*)al, n4);
    conv_tr_kernel<<<tr_grid, tr_block>>>(Wo, bh, bl);
    gemm_mma_kernel<<<gg, 256, GEMM_SMEM>>>(ah, al, bh, bl, bo, out_p, 0);
}

// round 5
// speedup vs baseline: 2.5634x; 1.2904x over previous
#include <cuda_runtime.h>
#include <cuda_bf16.h>
#include <math.h>
#include <stdint.h>

// Problem constants
#define BB 2
#define LL 2048
#define DD 4096
#define HH 32
#define HDIM 128
#define MM (BB*LL)          // 4096 rows
#define ATT_SCALE 0.08838834764831845f

// ---------------------------------------------------------------------------
// Scratch (allocation-free rule: __device__ globals)
// ---------------------------------------------------------------------------
__device__ __nv_bfloat16 g_ah[(size_t)MM*DD];                // A hi (x or ctx)
__device__ __nv_bfloat16 g_al[(size_t)MM*DD];                // A lo
__device__ __nv_bfloat16 g_bh[(size_t)DD*DD];                // W^T hi  [N,K]
__device__ __nv_bfloat16 g_bl[(size_t)DD*DD];                // W^T lo  [N,K]
__device__ __nv_bfloat16 g_qh[(size_t)MM*DD];                // q hi (scaled) [B,H,L,d]
__device__ __nv_bfloat16 g_ql[(size_t)MM*DD];
__device__ __nv_bfloat16 g_kh[(size_t)MM*DD];
__device__ __nv_bfloat16 g_kl[(size_t)MM*DD];
__device__ __nv_bfloat16 g_vh[(size_t)MM*DD];
__device__ __nv_bfloat16 g_vl[(size_t)MM*DD];

__device__ __forceinline__ uint32_t smem_u32(const void* p) {
    uint32_t a;
    asm("{ .reg .u64 t; cvta.to.shared.u64 t, %1; cvt.u32.u64 %0, t; }"
        : "=r"(a) : "l"(p));
    return a;
}

#define LDSM4(r, addr) \
    asm volatile("ldmatrix.sync.aligned.m8n8.x4.shared.b16 {%0,%1,%2,%3}, [%4];" \
        : "=r"((r)[0]), "=r"((r)[1]), "=r"((r)[2]), "=r"((r)[3]) : "r"(addr))
#define LDSM4T(r, addr) \
    asm volatile("ldmatrix.sync.aligned.m8n8.x4.trans.shared.b16 {%0,%1,%2,%3}, [%4];" \
        : "=r"((r)[0]), "=r"((r)[1]), "=r"((r)[2]), "=r"((r)[3]) : "r"(addr))

#define MMA_BF16(d, a, b0, b1) \
    asm volatile("mma.sync.aligned.m16n8k16.row.col.f32.bf16.bf16.f32 " \
        "{%0,%1,%2,%3}, {%4,%5,%6,%7}, {%8,%9}, {%0,%1,%2,%3};" \
        : "+f"((d)[0]), "+f"((d)[1]), "+f"((d)[2]), "+f"((d)[3]) \
        : "r"((a)[0]), "r"((a)[1]), "r"((a)[2]), "r"((a)[3]), "r"(b0), "r"(b1))

#define CP_ASYNC16(dst, src) \
    asm volatile("cp.async.cg.shared.global [%0], [%1], 16;" \
        :: "r"(dst), "l"(src) : "memory")
#define CP_COMMIT() asm volatile("cp.async.commit_group;" ::: "memory")
#define CP_WAIT1() asm volatile("cp.async.wait_group 1;" ::: "memory")
#define CP_WAIT0() asm volatile("cp.async.wait_group 0;" ::: "memory")

__device__ __forceinline__ uint32_t pack_bf2(float x, float y) {
    __nv_bfloat162 t;
    t.x = __float2bfloat16_rn(x);
    t.y = __float2bfloat16_rn(y);
    return *(uint32_t*)&t;
}

// ---------------------------------------------------------------------------
// Conversion kernels (fp32 -> bf16 hi/lo split)
// ---------------------------------------------------------------------------
struct __align__(8) bf16x4 { __nv_bfloat16 v[4]; };

__global__ __launch_bounds__(256) void conv_split_kernel(
    const float4* __restrict__ in, bf16x4* __restrict__ oh, bf16x4* __restrict__ ol, int n4)
{
    int i = blockIdx.x * 256 + threadIdx.x;
    if (i >= n4) return;
    float4 x = in[i];
    bf16x4 h, l;
    h.v[0] = __float2bfloat16_rn(x.x); l.v[0] = __float2bfloat16_rn(x.x - __bfloat162float(h.v[0]));
    h.v[1] = __float2bfloat16_rn(x.y); l.v[1] = __float2bfloat16_rn(x.y - __bfloat162float(h.v[1]));
    h.v[2] = __float2bfloat16_rn(x.z); l.v[2] = __float2bfloat16_rn(x.z - __bfloat162float(h.v[2]));
    h.v[3] = __float2bfloat16_rn(x.w); l.v[3] = __float2bfloat16_rn(x.w - __bfloat162float(h.v[3]));
    oh[i] = h;
    ol[i] = l;
}

// W [K,N] f32 row-major -> Wt hi/lo [N,K] bf16
__global__ __launch_bounds__(256) void conv_tr_kernel(
    const float* __restrict__ W, __nv_bfloat16* __restrict__ Th, __nv_bfloat16* __restrict__ Tl)
{
    __shared__ float sm[32][33];
    const int k0 = blockIdx.x * 32, n0 = blockIdx.y * 32;
    const int tx = threadIdx.x, ty = threadIdx.y;     // (32, 8)
#pragma unroll
    for (int i = 0; i < 4; i++)
        sm[ty + 8 * i][tx] = W[(size_t)(k0 + ty + 8 * i) * DD + n0 + tx];
    __syncthreads();
#pragma unroll
    for (int i = 0; i < 4; i++) {
        float v = sm[tx][ty + 8 * i];
        __nv_bfloat16 h = __float2bfloat16_rn(v);
        __nv_bfloat16 l = __float2bfloat16_rn(v - __bfloat162float(h));
        size_t idx = (size_t)(n0 + ty + 8 * i) * DD + k0 + tx;
        Th[idx] = h;
        Tl[idx] = l;
    }
}

// ---------------------------------------------------------------------------
// HMMA GEMM: out[M,N] = A[M,K] @ W[K,N] + bias, hi/lo bf16 3-term split.
// out_mode 0: fp32 row-major [M,N]
// out_mode 1: bf16 hi/lo split only, scaled, head-split [B,H,L,d]   (Q)
// out_mode 2: fp32 head-split + bf16 hi/lo split head-split         (K, V)
// ---------------------------------------------------------------------------
#define KCH 64
#define ROWSTR_B 144
#define TILE_BYTES (128 * ROWSTR_B)       // 18432
#define STAGE_BYTES (4 * TILE_BYTES)      // 73728
#define GEMM_SMEM (2 * STAGE_BYTES)       // 147456
#define NCHUNK (DD / KCH)                 // 64

__global__ __launch_bounds__(256, 1) void gemm_mma_kernel(
    const __nv_bfloat16* __restrict__ Ah, const __nv_bfloat16* __restrict__ Al,
    const __nv_bfloat16* __restrict__ Bh, const __nv_bfloat16* __restrict__ Bl,
    const float* __restrict__ bias, float* __restrict__ out,
    __nv_bfloat16* __restrict__ oh, __nv_bfloat16* __restrict__ ol,
    float scale, int out_mode)
{
    extern __shared__ __align__(16) char smem[];
    const uint32_t sb = smem_u32(smem);
    const int tid = threadIdx.x, lane = tid & 31, wid = tid >> 5;
    const int wm = wid >> 2;              // 0..1
    const int wn = wid & 3;               // 0..3
    const int m0 = blockIdx.y * 128;
    const int n0 = blockIdx.x * 128;

    const __nv_bfloat16* gsrc[4];
    gsrc[0] = Ah + (size_t)m0 * DD;
    gsrc[1] = Al + (size_t)m0 * DD;
    gsrc[2] = Bh + (size_t)n0 * DD;
    gsrc[3] = Bl + (size_t)n0 * DD;

    float acc[4][4][4];
#pragma unroll
    for (int i = 0; i < 4; i++)
#pragma unroll
        for (int j = 0; j < 4; j++)
#pragma unroll
            for (int e = 0; e < 4; e++) acc[i][j][e] = 0.f;

    const uint32_t a_off = (uint32_t)(wm * 64 + (lane & 15)) * ROWSTR_B + ((lane >> 4) << 4);
    const uint32_t b_off = (uint32_t)(wn * 32 + ((lane >> 4) << 3) + (lane & 7)) * ROWSTR_B
                           + (((lane >> 3) & 1) << 4);

#define LOAD_CHUNK(cc, buf) do {                                               \
    const uint32_t stage_ = sb + (uint32_t)(buf) * STAGE_BYTES;                \
    _Pragma("unroll")                                                          \
    for (int t_ = 0; t_ < 4; ++t_) {                                           \
        const __nv_bfloat16* gp_ = gsrc[t_] + (size_t)(cc) * KCH;              \
        _Pragma("unroll")                                                      \
        for (int i_ = 0; i_ < 4; ++i_) {                                       \
            int f_ = tid + i_ * 256;                                           \
            int r_ = f_ >> 3, s_ = f_ & 7;                                     \
            const void* src_ = gp_ + (size_t)r_ * DD + s_ * 8;                 \
            uint32_t dst_ = stage_ + t_ * TILE_BYTES + r_ * ROWSTR_B + s_ * 16;\
            CP_ASYNC16(dst_, src_);                                            \
        }                                                                      \
    }                                                                          \
    CP_COMMIT();                                                               \
} while (0)

    LOAD_CHUNK(0, 0);

#pragma unroll 1
    for (int c = 0; c < NCHUNK; ++c) {
        if (c + 1 < NCHUNK) {
            LOAD_CHUNK(c + 1, (c + 1) & 1);
            CP_WAIT1();
        } else {
            CP_WAIT0();
        }
        __syncthreads();

        const uint32_t stage = sb + (uint32_t)(c & 1) * STAGE_BYTES;
        const uint32_t a_h = stage + a_off;
        const uint32_t a_l = stage + TILE_BYTES + a_off;
        const uint32_t b_h = stage + 2 * TILE_BYTES + b_off;
        const uint32_t b_l = stage + 3 * TILE_BYTES + b_off;

#pragma unroll
        for (int kk = 0; kk < 4; ++kk) {
            uint32_t ah_[4][4], al_[4][4], bh_[2][4], bl_[2][4];
#pragma unroll
            for (int i = 0; i < 4; ++i) {
                LDSM4(ah_[i], a_h + i * 16 * ROWSTR_B + kk * 32);
                LDSM4(al_[i], a_l + i * 16 * ROWSTR_B + kk * 32);
            }
#pragma unroll
            for (int j = 0; j < 2; ++j) {
                LDSM4(bh_[j], b_h + j * 16 * ROWSTR_B + kk * 32);
                LDSM4(bl_[j], b_l + j * 16 * ROWSTR_B + kk * 32);
            }
#pragma unroll
            for (int i = 0; i < 4; ++i)
#pragma unroll
                for (int jn = 0; jn < 4; ++jn)
                    MMA_BF16(acc[i][jn], ah_[i], bh_[jn >> 1][(jn & 1) * 2],
                             bh_[jn >> 1][(jn & 1) * 2 + 1]);
#pragma unroll
            for (int i = 0; i < 4; ++i)
#pragma unroll
                for (int jn = 0; jn < 4; ++jn)
                    MMA_BF16(acc[i][jn], ah_[i], bl_[jn >> 1][(jn & 1) * 2],
                             bl_[jn >> 1][(jn & 1) * 2 + 1]);
#pragma unroll
            for (int i = 0; i < 4; ++i)
#pragma unroll
                for (int jn = 0; jn < 4; ++jn)
                    MMA_BF16(acc[i][jn], al_[i], bh_[jn >> 1][(jn & 1) * 2],
                             bh_[jn >> 1][(jn & 1) * 2 + 1]);
        }
        __syncthreads();
    }
#undef LOAD_CHUNK

    // epilogue
#pragma unroll
    for (int i = 0; i < 4; ++i) {
        const int r_lo = m0 + wm * 64 + i * 16 + (lane >> 2);
#pragma unroll
        for (int jn = 0; jn < 4; ++jn) {
            const int colg = n0 + wn * 32 + jn * 8 + (lane & 3) * 2;
            const float bv0 = bias[colg], bv1 = bias[colg + 1];
#pragma unroll
            for (int half = 0; half < 2; ++half) {
                const int row = r_lo + half * 8;
                float vx = acc[i][jn][half * 2 + 0] + bv0;
                float vy = acc[i][jn][half * 2 + 1] + bv1;
                if (out_mode == 0) {
                    float2 v; v.x = vx; v.y = vy;
                    *(float2*)(out + (size_t)row * DD + colg) = v;
                } else {
                    int b_ = row >> 11, l_ = row & 2047, h_ = colg >> 7, dd = colg & 127;
                    size_t idx = ((((size_t)b_ * HH + h_) * LL + l_) * HDIM) + dd;
                    if (out_mode == 2) {
                        float2 v; v.x = vx; v.y = vy;
                        *(float2*)(out + idx) = v;
                    }
                    float sx = vx * scale, sy = vy * scale;
                    __nv_bfloat16 hx = __float2bfloat16_rn(sx);
                    __nv_bfloat16 hy = __float2bfloat16_rn(sy);
                    float rx = sx - __bfloat162float(hx);
                    float ry = sy - __bfloat162float(hy);
                    __nv_bfloat162 hp; hp.x = hx; hp.y = hy;
                    __nv_bfloat162 lp; lp.x = __float2bfloat16_rn(rx); lp.y = __float2bfloat16_rn(ry);
                    *(uint32_t*)(oh + idx) = *(uint32_t*)&hp;
                    *(uint32_t*)(ol + idx) = *(uint32_t*)&lp;
                }
            }
        }
    }
}

// ---------------------------------------------------------------------------
// Flash attention (causal) with HMMA, bf16 hi/lo 3-term split.
// Grid (L/64, H, B), 128 threads (4 warps, 16 q-rows each).
// Writes ctx directly as bf16 hi/lo split, row-major [B*L, D] (feeds Wo GEMM).
// ---------------------------------------------------------------------------
#define AROWSTR 272                       // 128 bf16 = 256 B + 16 pad
#define ATILE (64 * AROWSTR)              // 17408
#define ATT_SMEM (6 * ATILE)              // 104448

__global__ __launch_bounds__(128, 2) void attn_mma_kernel(
    const __nv_bfloat16* __restrict__ qh, const __nv_bfloat16* __restrict__ ql,
    const __nv_bfloat16* __restrict__ kh, const __nv_bfloat16* __restrict__ kl,
    const __nv_bfloat16* __restrict__ vh, const __nv_bfloat16* __restrict__ vl,
    __nv_bfloat16* __restrict__ cth, __nv_bfloat16* __restrict__ ctl)
{
    extern __shared__ __align__(16) char smem[];
    const uint32_t sb = smem_u32(smem);
    const int tid = threadIdx.x, lane = tid & 31, wid = tid >> 5;
    const int wr = wid * 16;

    const int qt = blockIdx.x, h = blockIdx.y, b = blockIdx.z;
    const int q0 = qt * 64;
    const size_t hb = ((size_t)b * HH + h) * LL * HDIM;

    // load Q tiles (hi, lo)
    {
        const __nv_bfloat16* srcs[2] = { qh + hb, ql + hb };
#pragma unroll
        for (int t = 0; t < 2; ++t)
#pragma unroll
            for (int i = 0; i < 8; ++i) {
                int f = tid + i * 128;
                int r = f >> 4, s = f & 15;
                CP_ASYNC16(sb + t * ATILE + r * AROWSTR + s * 16,
                           srcs[t] + (size_t)(q0 + r) * HDIM + s * 8);
            }
        CP_COMMIT();
    }

    float o[16][4];
#pragma unroll
    for (int i = 0; i < 16; ++i)
#pragma unroll
        for (int e = 0; e < 4; ++e) o[i][e] = 0.f;
    float m_i[2] = { -1e30f, -1e30f };
    float l_i[2] = { 0.f, 0.f };

    // per-thread ldsm offsets
    const uint32_t qa_off = (uint32_t)(wr + (lane & 15)) * AROWSTR + ((lane >> 4) << 4);
    const uint32_t kb_off = (uint32_t)(((lane >> 4) << 3) + (lane & 7)) * AROWSTR
                            + (((lane >> 3) & 1) << 4);
    const uint32_t vb_off = (uint32_t)(((lane >> 3) & 1) * 8 + (lane & 7)) * AROWSTR
                            + ((lane >> 4) << 4);   // +8 cols = 16 bytes

#pragma unroll 1
    for (int kt = 0; kt <= qt; ++kt) {
        const int k0 = kt * 64;
        // load K/V tiles (hi, lo each)
        {
            const __nv_bfloat16* srcs[4] = { kh + hb, kl + hb, vh + hb, vl + hb };
#pragma unroll
            for (int t = 0; t < 4; ++t)
#pragma unroll
                for (int i = 0; i < 8; ++i) {
                    int f = tid + i * 128;
                    int r = f >> 4, s = f & 15;
                    CP_ASYNC16(sb + (2 + t) * ATILE + r * AROWSTR + s * 16,
                               srcs[t] + (size_t)(k0 + r) * HDIM + s * 8);
                }
            CP_COMMIT();
        }
        CP_WAIT0();
        __syncthreads();

        // ---- S = Qs @ K^T (3-term) ----
        float s[8][4];
#pragma unroll
        for (int i = 0; i < 8; ++i)
#pragma unroll
            for (int e = 0; e < 4; ++e) s[i][e] = 0.f;

#pragma unroll
        for (int kk = 0; kk < 8; ++kk) {
            uint32_t qa_h[4], qa_l[4], kb_h[4][4], kb_l[4][4];
            LDSM4(qa_h, sb + 0 * ATILE + qa_off + kk * 32);
            LDSM4(qa_l, sb + 1 * ATILE + qa_off + kk * 32);
#pragma unroll
            for (int g = 0; g < 4; ++g) {
                LDSM4(kb_h[g], sb + 2 * ATILE + g * 16 * AROWSTR + kb_off + kk * 32);
                LDSM4(kb_l[g], sb + 3 * ATILE + g * 16 * AROWSTR + kb_off + kk * 32);
            }
#pragma unroll
            for (int g = 0; g < 4; ++g)
#pragma unroll
                for (int j = 0; j < 2; ++j) {
                    const int nt = 2 * g + j;
                    MMA_BF16(s[nt], qa_h, kb_h[g][j * 2], kb_h[g][j * 2 + 1]);
                    MMA_BF16(s[nt], qa_l, kb_h[g][j * 2], kb_h[g][j * 2 + 1]);
                    MMA_BF16(s[nt], qa_h, kb_l[g][j * 2], kb_l[g][j * 2 + 1]);
                }
        }

        // ---- mask (diag tile) ----
        const int r0g = q0 + wr + (lane >> 2);
        if (kt == qt) {
#pragma unroll
            for (int nt = 0; nt < 8; ++nt) {
                const int cg = k0 + nt * 8 + (lane & 3) * 2;
#pragma unroll
                for (int e = 0; e < 4; ++e) {
                    const int rr = r0g + (e >> 1) * 8;
                    const int cc = cg + (e & 1);
                    if (cc > rr) s[nt][e] = -1e30f;
                }
            }
        }

        // ---- online softmax (rows r0 = lane>>2, r1 = r0+8) ----
        float scl[2];
#pragma unroll
        for (int rh = 0; rh < 2; ++rh) {
            float mx = -1e30f;
#pragma unroll
            for (int nt = 0; nt < 8; ++nt)
                mx = fmaxf(mx, fmaxf(s[nt][rh * 2], s[nt][rh * 2 + 1]));
            mx = fmaxf(mx, __shfl_xor_sync(0xffffffffu, mx, 1));
            mx = fmaxf(mx, __shfl_xor_sync(0xffffffffu, mx, 2));
            const float m_new = fmaxf(m_i[rh], mx);
            scl[rh] = __expf(m_i[rh] - m_new);
            float rs = 0.f;
#pragma unroll
            for (int nt = 0; nt < 8; ++nt) {
                float p0 = __expf(s[nt][rh * 2] - m_new);
                float p1 = __expf(s[nt][rh * 2 + 1] - m_new);
                s[nt][rh * 2] = p0;
                s[nt][rh * 2 + 1] = p1;
                rs += p0 + p1;
            }
            rs += __shfl_xor_sync(0xffffffffu, rs, 1);
            rs += __shfl_xor_sync(0xffffffffu, rs, 2);
            l_i[rh] = l_i[rh] * scl[rh] + rs;
            m_i[rh] = m_new;
        }
#pragma unroll
        for (int i = 0; i < 16; ++i) {
            o[i][0] *= scl[0]; o[i][1] *= scl[0];
            o[i][2] *= scl[1]; o[i][3] *= scl[1];
        }

        // ---- split P into bf16 hi/lo A-fragments ----
        uint32_t pa_h[4][4], pa_l[4][4];
#pragma unroll
        for (int kk = 0; kk < 4; ++kk) {
            const int t0 = 2 * kk, t1 = 2 * kk + 1;
            float ph[8], pr[8];
            const float pv[8] = { s[t0][0], s[t0][1], s[t0][2], s[t0][3],
                                  s[t1][0], s[t1][1], s[t1][2], s[t1][3] };
#pragma unroll
            for (int e = 0; e < 8; ++e) {
                __nv_bfloat16 hb_ = __float2bfloat16_rn(pv[e]);
                ph[e] = __bfloat162float(hb_);
                pr[e] = pv[e] - ph[e];
            }
            pa_h[kk][0] = pack_bf2(ph[0], ph[1]);
            pa_h[kk][1] = pack_bf2(ph[2], ph[3]);
            pa_h[kk][2] = pack_bf2(ph[4], ph[5]);
            pa_h[kk][3] = pack_bf2(ph[6], ph[7]);
            pa_l[kk][0] = pack_bf2(pr[0], pr[1]);
            pa_l[kk][1] = pack_bf2(pr[2], pr[3]);
            pa_l[kk][2] = pack_bf2(pr[4], pr[5]);
            pa_l[kk][3] = pack_bf2(pr[6], pr[7]);
        }

        // ---- O += P @ V (3-term) ----
#pragma unroll
        for (int g = 0; g < 8; ++g) {
#pragma unroll
            for (int kk = 0; kk < 4; ++kk) {
                uint32_t vb_h[4], vb_l[4];
                const uint32_t va = (uint32_t)(kk * 16) * AROWSTR + g * 32 + vb_off;
                LDSM4T(vb_h, sb + 4 * ATILE + va);
                LDSM4T(vb_l, sb + 5 * ATILE + va);
                const int nt0 = 2 * g, nt1 = 2 * g + 1;
                MMA_BF16(o[nt0], pa_h[kk], vb_h[0], vb_h[1]);
                MMA_BF16(o[nt1], pa_h[kk], vb_h[2], vb_h[3]);
                MMA_BF16(o[nt0], pa_l[kk], vb_h[0], vb_h[1]);
                MMA_BF16(o[nt1], pa_l[kk], vb_h[2], vb_h[3]);
                MMA_BF16(o[nt0], pa_h[kk], vb_l[0], vb_l[1]);
                MMA_BF16(o[nt1], pa_h[kk], vb_l[2], vb_l[3]);
            }
        }
        __syncthreads();   // V consumed; next iter may overwrite tiles
    }

    // ---- epilogue: ctx bf16 hi/lo, row-major [B*L, D] ----
    const float inv0 = 1.0f / l_i[0];
    const float inv1 = 1.0f / l_i[1];
    const int rg0 = b * LL + q0 + wr + (lane >> 2);
    const int rg1 = rg0 + 8;
#pragma unroll
    for (int nt = 0; nt < 16; ++nt) {
        const int col = h * HDIM + nt * 8 + (lane & 3) * 2;
        // row rg0: o[nt][0], o[nt][1]
        {
            float vx = o[nt][0] * inv0, vy = o[nt][1] * inv0;
            __nv_bfloat16 hx = __float2bfloat16_rn(vx), hy = __float2bfloat16_rn(vy);
            float rx = vx - __bfloat162float(hx), ry = vy - __bfloat162float(hy);
            __nv_bfloat162 hp; hp.x = hx; hp.y = hy;
            __nv_bfloat162 lp; lp.x = __float2bfloat16_rn(rx); lp.y = __float2bfloat16_rn(ry);
            size_t idx = (size_t)rg0 * DD + col;
            *(uint32_t*)(cth + idx) = *(uint32_t*)&hp;
            *(uint32_t*)(ctl + idx) = *(uint32_t*)&lp;
        }
        // row rg1: o[nt][2], o[nt][3]
        {
            float vx = o[nt][2] * inv1, vy = o[nt][3] * inv1;
            __nv_bfloat16 hx = __float2bfloat16_rn(vx), hy = __float2bfloat16_rn(vy);
            float rx = vx - __bfloat162float(hx), ry = vy - __bfloat162float(hy);
            __nv_bfloat162 hp; hp.x = hx; hp.y = hy;
            __nv_bfloat162 lp; lp.x = __float2bfloat16_rn(rx); lp.y = __float2bfloat16_rn(ry);
            size_t idx = (size_t)rg1 * DD + col;
            *(uint32_t*)(cth + idx) = *(uint32_t*)&hp;
            *(uint32_t*)(ctl + idx) = *(uint32_t*)&lp;
        }
    }
}

// ---------------------------------------------------------------------------
// Launch.  d_out layout: [ out (B*L*D) | k (B*H*L*d) | v (B*H*L*d) ]
// ---------------------------------------------------------------------------
extern "C" void kernel_launch(void* const* d_in, const int* in_sizes, int n_in,
                              void* d_out, int out_size)
{
    const float* x  = (const float*)d_in[0];
    const float* Wq = (const float*)d_in[2];
    const float* bq = (const float*)d_in[3];
    const float* Wk = (const float*)d_in[4];
    const float* bk = (const float*)d_in[5];
    const float* Wv = (const float*)d_in[6];
    const float* bv = (const float*)d_in[7];
    const float* Wo = (const float*)d_in[8];
    const float* bo = (const float*)d_in[9];

    float* out_p = (float*)d_out;
    float* k_out = out_p + (size_t)BB * LL * DD;
    float* v_out = k_out + (size_t)BB * HH * LL * HDIM;

    __nv_bfloat16 *ah, *al, *bh, *bl, *qh, *ql, *kh, *kl, *vh, *vl;
    cudaGetSymbolAddress((void**)&ah, g_ah);
    cudaGetSymbolAddress((void**)&al, g_al);
    cudaGetSymbolAddress((void**)&bh, g_bh);
    cudaGetSymbolAddress((void**)&bl, g_bl);
    cudaGetSymbolAddress((void**)&qh, g_qh);
    cudaGetSymbolAddress((void**)&ql, g_ql);
    cudaGetSymbolAddress((void**)&kh, g_kh);
    cudaGetSymbolAddress((void**)&kl, g_kl);
    cudaGetSymbolAddress((void**)&vh, g_vh);
    cudaGetSymbolAddress((void**)&vl, g_vl);

    cudaFuncSetAttribute(gemm_mma_kernel, cudaFuncAttributeMaxDynamicSharedMemorySize, GEMM_SMEM);
    cudaFuncSetAttribute(attn_mma_kernel, cudaFuncAttributeMaxDynamicSharedMemorySize, ATT_SMEM);

    const int n4 = MM * DD / 4;
    const int cs_blocks = n4 / 256;
    dim3 tr_grid(DD / 32, DD / 32);
    dim3 tr_block(32, 8);
    dim3 gg(DD / 128, MM / 128);

    // split A = x
    conv_split_kernel<<<cs_blocks, 256>>>((const float4*)x, (bf16x4*)ah, (bf16x4*)al, n4);

    // Q projection -> bf16 split, pre-scaled
    conv_tr_kernel<<<tr_grid, tr_block>>>(Wq, bh, bl);
    gemm_mma_kernel<<<gg, 256, GEMM_SMEM>>>(ah, al, bh, bl, bq, nullptr, qh, ql, ATT_SCALE, 1);

    // K projection -> fp32 k_out + bf16 split
    conv_tr_kernel<<<tr_grid, tr_block>>>(Wk, bh, bl);
    gemm_mma_kernel<<<gg, 256, GEMM_SMEM>>>(ah, al, bh, bl, bk, k_out, kh, kl, 1.0f, 2);

    // V projection -> fp32 v_out + bf16 split
    conv_tr_kernel<<<tr_grid, tr_block>>>(Wv, bh, bl);
    gemm_mma_kernel<<<gg, 256, GEMM_SMEM>>>(ah, al, bh, bl, bv, v_out, vh, vl, 1.0f, 2);

    // attention (HMMA) -> ctx bf16 split directly into ah/al
    dim3 ag(LL / 64, HH, BB);
    attn_mma_kernel<<<ag, 128, ATT_SMEM>>>(qh, ql, kh, kl, vh, vl, ah, al);

    // output projection
    conv_tr_kernel<<<tr_grid, tr_block>>>(Wo, bh, bl);
    gemm_mma_kernel<<<gg, 256, GEMM_SMEM>>>(ah, al, bh, bl, bo, out_p, nullptr, nullptr, 1.0f, 0);
}

// round 6
// speedup vs baseline: 3.6575x; 1.4268x over previous
#include <cuda_runtime.h>
#include <cuda_fp16.h>
#include <math.h>
#include <stdint.h>

// Problem constants
#define BB 2
#define LL 2048
#define DD 4096
#define HH 32
#define HDIM 128
#define MM (BB*LL)          // 4096 rows
#define ATT_SCALE 0.08838834764831845f

// ---------------------------------------------------------------------------
// Scratch (allocation-free rule: __device__ globals)
// ---------------------------------------------------------------------------
__device__ __half g_ah[(size_t)MM*DD];       // A hi (x or ctx)
__device__ __half g_al[(size_t)MM*DD];       // A lo
__device__ __half g_bh[(size_t)DD*DD];       // W^T fp16  [N,K]
__device__ __half g_qh[(size_t)MM*DD];       // q hi (scaled) [B,H,L,d]
__device__ __half g_ql[(size_t)MM*DD];       // q lo
__device__ __half g_kh[(size_t)MM*DD];       // k fp16
__device__ __half g_vh[(size_t)MM*DD];       // v fp16

__device__ __forceinline__ uint32_t smem_u32(const void* p) {
    uint32_t a;
    asm("{ .reg .u64 t; cvta.to.shared.u64 t, %1; cvt.u32.u64 %0, t; }"
        : "=r"(a) : "l"(p));
    return a;
}

#define LDSM4(r, addr) \
    asm volatile("ldmatrix.sync.aligned.m8n8.x4.shared.b16 {%0,%1,%2,%3}, [%4];" \
        : "=r"((r)[0]), "=r"((r)[1]), "=r"((r)[2]), "=r"((r)[3]) : "r"(addr))
#define LDSM4T(r, addr) \
    asm volatile("ldmatrix.sync.aligned.m8n8.x4.trans.shared.b16 {%0,%1,%2,%3}, [%4];" \
        : "=r"((r)[0]), "=r"((r)[1]), "=r"((r)[2]), "=r"((r)[3]) : "r"(addr))

#define MMA_F16(d, a, b0, b1) \
    asm volatile("mma.sync.aligned.m16n8k16.row.col.f32.f16.f16.f32 " \
        "{%0,%1,%2,%3}, {%4,%5,%6,%7}, {%8,%9}, {%0,%1,%2,%3};" \
        : "+f"((d)[0]), "+f"((d)[1]), "+f"((d)[2]), "+f"((d)[3]) \
        : "r"((a)[0]), "r"((a)[1]), "r"((a)[2]), "r"((a)[3]), "r"(b0), "r"(b1))

#define CP_ASYNC16(dst, src) \
    asm volatile("cp.async.cg.shared.global [%0], [%1], 16;" \
        :: "r"(dst), "l"(src) : "memory")
#define CP_COMMIT() asm volatile("cp.async.commit_group;" ::: "memory")
#define CP_WAIT1() asm volatile("cp.async.wait_group 1;" ::: "memory")
#define CP_WAIT0() asm volatile("cp.async.wait_group 0;" ::: "memory")

__device__ __forceinline__ uint32_t pack_h2(float x, float y) {
    __half2 t = __floats2half2_rn(x, y);
    return *(uint32_t*)&t;
}

// ---------------------------------------------------------------------------
// Conversion kernels
// ---------------------------------------------------------------------------
struct __align__(8) h16x4 { __half v[4]; };

__global__ __launch_bounds__(256) void conv_split_kernel(
    const float4* __restrict__ in, h16x4* __restrict__ oh, h16x4* __restrict__ ol, int n4)
{
    int i = blockIdx.x * 256 + threadIdx.x;
    if (i >= n4) return;
    float4 x = in[i];
    h16x4 h, l;
    h.v[0] = __float2half_rn(x.x); l.v[0] = __float2half_rn(x.x - __half2float(h.v[0]));
    h.v[1] = __float2half_rn(x.y); l.v[1] = __float2half_rn(x.y - __half2float(h.v[1]));
    h.v[2] = __float2half_rn(x.z); l.v[2] = __float2half_rn(x.z - __half2float(h.v[2]));
    h.v[3] = __float2half_rn(x.w); l.v[3] = __float2half_rn(x.w - __half2float(h.v[3]));
    oh[i] = h;
    ol[i] = l;
}

// W [K,N] f32 row-major -> Wt fp16 [N,K]
__global__ __launch_bounds__(256) void conv_tr_kernel(
    const float* __restrict__ W, __half* __restrict__ Th)
{
    __shared__ float sm[32][33];
    const int k0 = blockIdx.x * 32, n0 = blockIdx.y * 32;
    const int tx = threadIdx.x, ty = threadIdx.y;     // (32, 8)
#pragma unroll
    for (int i = 0; i < 4; i++)
        sm[ty + 8 * i][tx] = W[(size_t)(k0 + ty + 8 * i) * DD + n0 + tx];
    __syncthreads();
#pragma unroll
    for (int i = 0; i < 4; i++) {
        float v = sm[tx][ty + 8 * i];
        Th[(size_t)(n0 + ty + 8 * i) * DD + k0 + tx] = __float2half_rn(v);
    }
}

// ---------------------------------------------------------------------------
// HMMA GEMM: out[M,N] = A[M,K] @ W[K,N] + bias, fp16 2-term split (A hi/lo).
// out_mode 0: fp32 row-major [M,N]
// out_mode 1: fp16 hi/lo split only, scaled, head-split [B,H,L,d]   (Q)
// out_mode 2: fp32 head-split + fp16 (single) head-split            (K, V)
// 3-stage cp.async pipeline, CTA 128x128, 8 warps 2x4.
// ---------------------------------------------------------------------------
#define KCH 64
#define ROWSTR_B 144
#define TILE_BYTES (128 * ROWSTR_B)       // 18432
#define STAGE_BYTES (3 * TILE_BYTES)      // 55296  (Ah, Al, B)
#define GEMM_SMEM (3 * STAGE_BYTES)       // 165888
#define NCHUNK (DD / KCH)                 // 64

__global__ __launch_bounds__(256, 1) void gemm_mma_kernel(
    const __half* __restrict__ Ah, const __half* __restrict__ Al,
    const __half* __restrict__ B,
    const float* __restrict__ bias, float* __restrict__ out,
    __half* __restrict__ oh, __half* __restrict__ ol,
    float scale, int out_mode)
{
    extern __shared__ __align__(16) char smem[];
    const uint32_t sb = smem_u32(smem);
    const int tid = threadIdx.x, lane = tid & 31, wid = tid >> 5;
    const int wm = wid >> 2;              // 0..1
    const int wn = wid & 3;               // 0..3
    const int m0 = blockIdx.y * 128;
    const int n0 = blockIdx.x * 128;

    const __half* gsrc[3];
    gsrc[0] = Ah + (size_t)m0 * DD;
    gsrc[1] = Al + (size_t)m0 * DD;
    gsrc[2] = B + (size_t)n0 * DD;

    float acc[4][4][4];
#pragma unroll
    for (int i = 0; i < 4; i++)
#pragma unroll
        for (int j = 0; j < 4; j++)
#pragma unroll
            for (int e = 0; e < 4; e++) acc[i][j][e] = 0.f;

    const uint32_t a_off = (uint32_t)(wm * 64 + (lane & 15)) * ROWSTR_B + ((lane >> 4) << 4);
    const uint32_t b_off = (uint32_t)(wn * 32 + ((lane >> 4) << 3) + (lane & 7)) * ROWSTR_B
                           + (((lane >> 3) & 1) << 4);

#define LOAD_CHUNK(cc, st) do {                                                \
    const uint32_t stage_ = sb + (uint32_t)(st) * STAGE_BYTES;                 \
    _Pragma("unroll")                                                          \
    for (int t_ = 0; t_ < 3; ++t_) {                                           \
        const __half* gp_ = gsrc[t_] + (size_t)(cc) * KCH;                     \
        _Pragma("unroll")                                                      \
        for (int i_ = 0; i_ < 4; ++i_) {                                       \
            int f_ = tid + i_ * 256;                                           \
            int r_ = f_ >> 3, s_ = f_ & 7;                                     \
            const void* src_ = gp_ + (size_t)r_ * DD + s_ * 8;                 \
            uint32_t dst_ = stage_ + t_ * TILE_BYTES + r_ * ROWSTR_B + s_ * 16;\
            CP_ASYNC16(dst_, src_);                                            \
        }                                                                      \
    }                                                                          \
    CP_COMMIT();                                                               \
} while (0)

    LOAD_CHUNK(0, 0);
    LOAD_CHUNK(1, 1);

#pragma unroll 1
    for (int c = 0; c < NCHUNK; ++c) {
        if (c < NCHUNK - 1) { CP_WAIT1(); } else { CP_WAIT0(); }
        __syncthreads();
        if (c + 2 < NCHUNK) LOAD_CHUNK(c + 2, (c + 2) % 3);

        const uint32_t stage = sb + (uint32_t)(c % 3) * STAGE_BYTES;
        const uint32_t a_h = stage + a_off;
        const uint32_t a_l = stage + TILE_BYTES + a_off;
        const uint32_t b_s = stage + 2 * TILE_BYTES + b_off;

#pragma unroll
        for (int kk = 0; kk < 4; ++kk) {
            uint32_t ah_[4][4], al_[4][4], bf_[2][4];
#pragma unroll
            for (int i = 0; i < 4; ++i) {
                LDSM4(ah_[i], a_h + i * 16 * ROWSTR_B + kk * 32);
                LDSM4(al_[i], a_l + i * 16 * ROWSTR_B + kk * 32);
            }
#pragma unroll
            for (int j = 0; j < 2; ++j)
                LDSM4(bf_[j], b_s + j * 16 * ROWSTR_B + kk * 32);
#pragma unroll
            for (int i = 0; i < 4; ++i)
#pragma unroll
                for (int jn = 0; jn < 4; ++jn)
                    MMA_F16(acc[i][jn], ah_[i], bf_[jn >> 1][(jn & 1) * 2],
                            bf_[jn >> 1][(jn & 1) * 2 + 1]);
#pragma unroll
            for (int i = 0; i < 4; ++i)
#pragma unroll
                for (int jn = 0; jn < 4; ++jn)
                    MMA_F16(acc[i][jn], al_[i], bf_[jn >> 1][(jn & 1) * 2],
                            bf_[jn >> 1][(jn & 1) * 2 + 1]);
        }
        __syncthreads();
    }
#undef LOAD_CHUNK

    // epilogue
#pragma unroll
    for (int i = 0; i < 4; ++i) {
        const int r_lo = m0 + wm * 64 + i * 16 + (lane >> 2);
#pragma unroll
        for (int jn = 0; jn < 4; ++jn) {
            const int colg = n0 + wn * 32 + jn * 8 + (lane & 3) * 2;
            const float bv0 = bias[colg], bv1 = bias[colg + 1];
#pragma unroll
            for (int half_ = 0; half_ < 2; ++half_) {
                const int row = r_lo + half_ * 8;
                float vx = acc[i][jn][half_ * 2 + 0] + bv0;
                float vy = acc[i][jn][half_ * 2 + 1] + bv1;
                if (out_mode == 0) {
                    float2 v; v.x = vx; v.y = vy;
                    *(float2*)(out + (size_t)row * DD + colg) = v;
                } else {
                    int b_ = row >> 11, l_ = row & 2047, h_ = colg >> 7, dd = colg & 127;
                    size_t idx = ((((size_t)b_ * HH + h_) * LL + l_) * HDIM) + dd;
                    if (out_mode == 2) {
                        float2 v; v.x = vx; v.y = vy;
                        *(float2*)(out + idx) = v;
                        *(uint32_t*)(oh + idx) = pack_h2(vx, vy);
                    } else {
                        // mode 1: scaled hi/lo split
                        float sx = vx * scale, sy = vy * scale;
                        __half hx = __float2half_rn(sx), hy = __float2half_rn(sy);
                        float rx = sx - __half2float(hx), ry = sy - __half2float(hy);
                        __half2 hp; hp.x = hx; hp.y = hy;
                        *(uint32_t*)(oh + idx) = *(uint32_t*)&hp;
                        *(uint32_t*)(ol + idx) = pack_h2(rx, ry);
                    }
                }
            }
        }
    }
}

// ---------------------------------------------------------------------------
// Flash attention (causal), HMMA fp16 2-term.
// Grid (L/64, H, B), 128 threads (4 warps, 16 q-rows each).
// Q split hi/lo; K, V single fp16, double-buffered K/V prefetch.
// Writes ctx as fp16 hi/lo split, row-major [B*L, D] (feeds Wo GEMM).
// ---------------------------------------------------------------------------
#define AROWSTR 272                       // 128 fp16 = 256 B + 16 pad
#define ATILE (64 * AROWSTR)              // 17408
#define ATT_SMEM (6 * ATILE)              // 104448: Qh, Ql, K0, V0, K1, V1

__global__ __launch_bounds__(128, 2) void attn_mma_kernel(
    const __half* __restrict__ qh, const __half* __restrict__ ql,
    const __half* __restrict__ kh, const __half* __restrict__ vh,
    __half* __restrict__ cth, __half* __restrict__ ctl)
{
    extern __shared__ __align__(16) char smem[];
    const uint32_t sb = smem_u32(smem);
    const int tid = threadIdx.x, lane = tid & 31, wid = tid >> 5;
    const int wr = wid * 16;

    const int qt = blockIdx.x, h = blockIdx.y, b = blockIdx.z;
    const int q0 = qt * 64;
    const size_t hb = ((size_t)b * HH + h) * LL * HDIM;

    // load Q tiles (hi, lo)
    {
        const __half* srcs[2] = { qh + hb, ql + hb };
#pragma unroll
        for (int t = 0; t < 2; ++t)
#pragma unroll
            for (int i = 0; i < 8; ++i) {
                int f = tid + i * 128;
                int r = f >> 4, s = f & 15;
                CP_ASYNC16(sb + t * ATILE + r * AROWSTR + s * 16,
                           srcs[t] + (size_t)(q0 + r) * HDIM + s * 8);
            }
        CP_COMMIT();
    }

#define LOAD_KV(kt_, buf_) do {                                                \
    const int k0_ = (kt_) * 64;                                                \
    const __half* srcs_[2] = { kh + hb, vh + hb };                             \
    _Pragma("unroll")                                                          \
    for (int t_ = 0; t_ < 2; ++t_)                                             \
        _Pragma("unroll")                                                      \
        for (int i_ = 0; i_ < 8; ++i_) {                                       \
            int f_ = tid + i_ * 128;                                           \
            int r_ = f_ >> 4, s_ = f_ & 15;                                    \
            CP_ASYNC16(sb + (2 + 2 * (buf_) + t_) * ATILE + r_ * AROWSTR + s_ * 16, \
                       srcs_[t_] + (size_t)(k0_ + r_) * HDIM + s_ * 8);        \
        }                                                                      \
    CP_COMMIT();                                                               \
} while (0)

    LOAD_KV(0, 0);

    float o[16][4];
#pragma unroll
    for (int i = 0; i < 16; ++i)
#pragma unroll
        for (int e = 0; e < 4; ++e) o[i][e] = 0.f;
    float m_i[2] = { -1e30f, -1e30f };
    float l_i[2] = { 0.f, 0.f };

    const uint32_t qa_off = (uint32_t)(wr + (lane & 15)) * AROWSTR + ((lane >> 4) << 4);
    const uint32_t kb_off = (uint32_t)(((lane >> 4) << 3) + (lane & 7)) * AROWSTR
                            + (((lane >> 3) & 1) << 4);
    const uint32_t vb_off = (uint32_t)(((lane >> 3) & 1) * 8 + (lane & 7)) * AROWSTR
                            + ((lane >> 4) << 4);

#pragma unroll 1
    for (int kt = 0; kt <= qt; ++kt) {
        const int k0 = kt * 64;
        __syncthreads();                            // prior tile reads done
        if (kt + 1 <= qt) {
            LOAD_KV(kt + 1, (kt + 1) & 1);
            CP_WAIT1();
        } else {
            CP_WAIT0();
        }
        __syncthreads();                            // tile kt visible to all

        const uint32_t kt_s = sb + (2 + 2 * (kt & 1)) * ATILE;
        const uint32_t vt_s = sb + (3 + 2 * (kt & 1)) * ATILE;

        // ---- S = Q @ K^T (2-term) ----
        float s[8][4];
#pragma unroll
        for (int i = 0; i < 8; ++i)
#pragma unroll
            for (int e = 0; e < 4; ++e) s[i][e] = 0.f;

#pragma unroll
        for (int kk = 0; kk < 8; ++kk) {
            uint32_t qa_h[4], qa_l[4], kb_[4][4];
            LDSM4(qa_h, sb + 0 * ATILE + qa_off + kk * 32);
            LDSM4(qa_l, sb + 1 * ATILE + qa_off + kk * 32);
#pragma unroll
            for (int g = 0; g < 4; ++g)
                LDSM4(kb_[g], kt_s + g * 16 * AROWSTR + kb_off + kk * 32);
#pragma unroll
            for (int g = 0; g < 4; ++g)
#pragma unroll
                for (int j = 0; j < 2; ++j)
                    MMA_F16(s[2 * g + j], qa_h, kb_[g][j * 2], kb_[g][j * 2 + 1]);
#pragma unroll
            for (int g = 0; g < 4; ++g)
#pragma unroll
                for (int j = 0; j < 2; ++j)
                    MMA_F16(s[2 * g + j], qa_l, kb_[g][j * 2], kb_[g][j * 2 + 1]);
        }

        // ---- mask (diag tile) ----
        const int r0g = q0 + wr + (lane >> 2);
        if (kt == qt) {
#pragma unroll
            for (int nt = 0; nt < 8; ++nt) {
                const int cg = k0 + nt * 8 + (lane & 3) * 2;
#pragma unroll
                for (int e = 0; e < 4; ++e) {
                    const int rr = r0g + (e >> 1) * 8;
                    const int cc = cg + (e & 1);
                    if (cc > rr) s[nt][e] = -1e30f;
                }
            }
        }

        // ---- online softmax ----
        float scl[2];
#pragma unroll
        for (int rh = 0; rh < 2; ++rh) {
            float mx = -1e30f;
#pragma unroll
            for (int nt = 0; nt < 8; ++nt)
                mx = fmaxf(mx, fmaxf(s[nt][rh * 2], s[nt][rh * 2 + 1]));
            mx = fmaxf(mx, __shfl_xor_sync(0xffffffffu, mx, 1));
            mx = fmaxf(mx, __shfl_xor_sync(0xffffffffu, mx, 2));
            const float m_new = fmaxf(m_i[rh], mx);
            scl[rh] = __expf(m_i[rh] - m_new);
            float rs = 0.f;
#pragma unroll
            for (int nt = 0; nt < 8; ++nt) {
                float p0 = __expf(s[nt][rh * 2] - m_new);
                float p1 = __expf(s[nt][rh * 2 + 1] - m_new);
                s[nt][rh * 2] = p0;
                s[nt][rh * 2 + 1] = p1;
                rs += p0 + p1;
            }
            rs += __shfl_xor_sync(0xffffffffu, rs, 1);
            rs += __shfl_xor_sync(0xffffffffu, rs, 2);
            l_i[rh] = l_i[rh] * scl[rh] + rs;
            m_i[rh] = m_new;
        }
#pragma unroll
        for (int i = 0; i < 16; ++i) {
            o[i][0] *= scl[0]; o[i][1] *= scl[0];
            o[i][2] *= scl[1]; o[i][3] *= scl[1];
        }

        // ---- split P into fp16 hi/lo A-fragments ----
        uint32_t pa_h[4][4], pa_l[4][4];
#pragma unroll
        for (int kk = 0; kk < 4; ++kk) {
            const int t0 = 2 * kk, t1 = 2 * kk + 1;
            const float pv[8] = { s[t0][0], s[t0][1], s[t0][2], s[t0][3],
                                  s[t1][0], s[t1][1], s[t1][2], s[t1][3] };
            float ph[8], pr[8];
#pragma unroll
            for (int e = 0; e < 8; ++e) {
                __half hh = __float2half_rn(pv[e]);
                ph[e] = __half2float(hh);
                pr[e] = pv[e] - ph[e];
            }
            pa_h[kk][0] = pack_h2(ph[0], ph[1]);
            pa_h[kk][1] = pack_h2(ph[2], ph[3]);
            pa_h[kk][2] = pack_h2(ph[4], ph[5]);
            pa_h[kk][3] = pack_h2(ph[6], ph[7]);
            pa_l[kk][0] = pack_h2(pr[0], pr[1]);
            pa_l[kk][1] = pack_h2(pr[2], pr[3]);
            pa_l[kk][2] = pack_h2(pr[4], pr[5]);
            pa_l[kk][3] = pack_h2(pr[6], pr[7]);
        }

        // ---- O += P @ V (2-term) ----
#pragma unroll
        for (int g = 0; g < 8; ++g) {
            const int nt0 = 2 * g, nt1 = 2 * g + 1;
#pragma unroll
            for (int kk = 0; kk < 4; ++kk) {
                uint32_t vb_[4];
                LDSM4T(vb_, vt_s + (uint32_t)(kk * 16) * AROWSTR + g * 32 + vb_off);
                MMA_F16(o[nt0], pa_h[kk], vb_[0], vb_[1]);
                MMA_F16(o[nt1], pa_h[kk], vb_[2], vb_[3]);
                MMA_F16(o[nt0], pa_l[kk], vb_[0], vb_[1]);
                MMA_F16(o[nt1], pa_l[kk], vb_[2], vb_[3]);
            }
        }
    }
#undef LOAD_KV

    // ---- epilogue: ctx fp16 hi/lo, row-major [B*L, D] ----
    const float inv0 = 1.0f / l_i[0];
    const float inv1 = 1.0f / l_i[1];
    const int rg0 = b * LL + q0 + wr + (lane >> 2);
    const int rg1 = rg0 + 8;
#pragma unroll
    for (int nt = 0; nt < 16; ++nt) {
        const int col = h * HDIM + nt * 8 + (lane & 3) * 2;
        {
            float vx = o[nt][0] * inv0, vy = o[nt][1] * inv0;
            __half hx = __float2half_rn(vx), hy = __float2half_rn(vy);
            float rx = vx - __half2float(hx), ry = vy - __half2float(hy);
            __half2 hp; hp.x = hx; hp.y = hy;
            size_t idx = (size_t)rg0 * DD + col;
            *(uint32_t*)(cth + idx) = *(uint32_t*)&hp;
            *(uint32_t*)(ctl + idx) = pack_h2(rx, ry);
        }
        {
            float vx = o[nt][2] * inv1, vy = o[nt][3] * inv1;
            __half hx = __float2half_rn(vx), hy = __float2half_rn(vy);
            float rx = vx - __half2float(hx), ry = vy - __half2float(hy);
            __half2 hp; hp.x = hx; hp.y = hy;
            size_t idx = (size_t)rg1 * DD + col;
            *(uint32_t*)(cth + idx) = *(uint32_t*)&hp;
            *(uint32_t*)(ctl + idx) = pack_h2(rx, ry);
        }
    }
}

// ---------------------------------------------------------------------------
// Launch.  d_out layout: [ out (B*L*D) | k (B*H*L*d) | v (B*H*L*d) ]
// ---------------------------------------------------------------------------
extern "C" void kernel_launch(void* const* d_in, const int* in_sizes, int n_in,
                              void* d_out, int out_size)
{
    const float* x  = (const float*)d_in[0];
    const float* Wq = (const float*)d_in[2];
    const float* bq = (const float*)d_in[3];
    const float* Wk = (const float*)d_in[4];
    const float* bk = (const float*)d_in[5];
    const float* Wv = (const float*)d_in[6];
    const float* bv = (const float*)d_in[7];
    const float* Wo = (const float*)d_in[8];
    const float* bo = (const float*)d_in[9];

    float* out_p = (float*)d_out;
    float* k_out = out_p + (size_t)BB * LL * DD;
    float* v_out = k_out + (size_t)BB * HH * LL * HDIM;

    __half *ah, *al, *bh, *qh, *ql, *kh, *vh;
    cudaGetSymbolAddress((void**)&ah, g_ah);
    cudaGetSymbolAddress((void**)&al, g_al);
    cudaGetSymbolAddress((void**)&bh, g_bh);
    cudaGetSymbolAddress((void**)&qh, g_qh);
    cudaGetSymbolAddress((void**)&ql, g_ql);
    cudaGetSymbolAddress((void**)&kh, g_kh);
    cudaGetSymbolAddress((void**)&vh, g_vh);

    cudaFuncSetAttribute(gemm_mma_kernel, cudaFuncAttributeMaxDynamicSharedMemorySize, GEMM_SMEM);
    cudaFuncSetAttribute(attn_mma_kernel, cudaFuncAttributeMaxDynamicSharedMemorySize, ATT_SMEM);

    const int n4 = MM * DD / 4;
    const int cs_blocks = n4 / 256;
    dim3 tr_grid(DD / 32, DD / 32);
    dim3 tr_block(32, 8);
    dim3 gg(DD / 128, MM / 128);

    // split A = x (fp16 hi/lo)
    conv_split_kernel<<<cs_blocks, 256>>>((const float4*)x, (h16x4*)ah, (h16x4*)al, n4);

    // Q projection -> fp16 split, pre-scaled
    conv_tr_kernel<<<tr_grid, tr_block>>>(Wq, bh);
    gemm_mma_kernel<<<gg, 256, GEMM_SMEM>>>(ah, al, bh, bq, nullptr, qh, ql, ATT_SCALE, 1);

    // K projection -> fp32 k_out + fp16
    conv_tr_kernel<<<tr_grid, tr_block>>>(Wk, bh);
    gemm_mma_kernel<<<gg, 256, GEMM_SMEM>>>(ah, al, bh, bk, k_out, kh, nullptr, 1.0f, 2);

    // V projection -> fp32 v_out + fp16
    conv_tr_kernel<<<tr_grid, tr_block>>>(Wv, bh);
    gemm_mma_kernel<<<gg, 256, GEMM_SMEM>>>(ah, al, bh, bv, v_out, vh, nullptr, 1.0f, 2);

    // attention -> ctx fp16 split directly into ah/al
    dim3 ag(LL / 64, HH, BB);
    attn_mma_kernel<<<ag, 128, ATT_SMEM>>>(qh, ql, kh, vh, ah, al);

    // output projection
    conv_tr_kernel<<<tr_grid, tr_block>>>(Wo, bh);
    gemm_mma_kernel<<<gg, 256, GEMM_SMEM>>>(ah, al, bh, bo, out_p, nullptr, nullptr, 1.0f, 0);
}